// round 3
// baseline (speedup 1.0000x reference)
#include <cuda_runtime.h>

namespace {

constexpr int NQ  = 14;
constexpr int DIM = 1 << NQ;          // 16384 amplitudes
constexpr int TPB = 1024;
constexpr int NL  = 6;                // variational depth
constexpr int SMEM_SLOTS = DIM + DIM / 16;   // skewed layout

// Low-nibble pairing masks (QM) and parity-row nibbles (QPN) for wires 10..13
// at layer L (k = L+1 ladders applied).  Derived from
//   m_w = sum_r C(k,r) e_{w+r}   (e_j = bit 13-j)
//   p_w = sum_{d} C(k-1+d, d) e_{w-d}
// and hand-verified for k = 1..6.
constexpr int QM [6][4] = {{12,6,3,1},{10,5,2,1},{15,7,3,1},{8,4,2,1},{12,6,3,1},{10,5,2,1}};
constexpr int QPN[6][4] = {{8,12,14,15},{8,4,10,5},{8,12,6,3},{8,4,2,1},{8,12,14,15},{8,4,10,5}};

__device__ __forceinline__ int SLOT(int t) { return t + (t >> 4); }

__device__ __forceinline__ float2 cmul(float2 a, float2 b) {
    return make_float2(a.x * b.x - a.y * b.y, a.x * b.y + a.y * b.x);
}

// RY pair rotation: A' = c A - s B ; B' = s A + c B  (A = 0-component).
// Role reversal (when A is actually the 1-component) is handled by negating s.
__device__ __forceinline__ void rotp(float2& A, float2& B, float c, float s) {
    float2 a = A, b = B;
    A = make_float2(fmaf(c, a.x, -s * b.x), fmaf(c, a.y, -s * b.y));
    B = make_float2(fmaf(s, a.x,  c * b.x), fmaf(s, a.y,  c * b.y));
}

// Rotation over a 16-amplitude register group. M = XOR pairing mask,
// PN = parity-row nibble (both compile-time -> static register indexing).
template<int M, int PN>
__device__ __forceinline__ void rot16(float2* z, float c, float s) {
    constexpr int PIV = M & (-M);
    #pragma unroll
    for (int v = 0; v < 16; ++v) {
        if ((v & PIV) == 0) {
            float se = (__popc(v & PN) & 1) ? -s : s;
            rotp(z[v], z[v ^ M], c, se);
        }
    }
}

// 5 fused two-wire passes covering wires (0,1)..(8,9).  Masks/parities runtime.
__device__ __forceinline__ void two_wire_passes(
    float2* __restrict__ st, int tid,
    const unsigned* __restrict__ MS, const unsigned* __restrict__ PS,
    const float* __restrict__ CC, const float* __restrict__ SS)
{
    #pragma unroll 1
    for (int pp = 0; pp < 5; ++pp) {
        const int w  = 2 * pp;
        const int bp = 12 - w;                 // top bits of mA,mB live at bp,bp+1
        const int mA = (int)MS[w],     mB = (int)MS[w + 1];
        const int pA = (int)PS[w],     pB = (int)PS[w + 1];
        const float c0 = CC[w],     s0 = SS[w];
        const float c1 = CC[w + 1], s1 = SS[w + 1];
        #pragma unroll
        for (int it = 0; it < DIM / 4 / TPB; ++it) {
            int g = tid + it * TPB;
            // coset representative: insert two zero bits at positions bp, bp+1
            int t   = ((g >> bp) << (bp + 2)) | (g & ((1 << bp) - 1));
            int i00 = SLOT(t);
            int i10 = SLOT(t ^ mA);
            int i01 = SLOT(t ^ mB);
            int i11 = SLOT(t ^ (mA ^ mB));
            float2 a00 = st[i00], a10 = st[i10], a01 = st[i01], a11 = st[i11];
            float s0e = (__popc(t & pA) & 1) ? -s0 : s0;
            float s1e = (__popc(t & pB) & 1) ? -s1 : s1;
            // wire w   (sign invariant under ^mB since pA.mB = 0)
            rotp(a00, a10, c0, s0e);
            rotp(a01, a11, c0, s0e);
            // wire w+1 (sign invariant under ^mA since pB.mA = 0)
            rotp(a00, a01, c1, s1e);
            rotp(a10, a11, c1, s1e);
            st[i00] = a00; st[i10] = a10; st[i01] = a01; st[i11] = a11;
        }
        __syncthreads();
    }
}

// One fused pass for wires 10..13: each 16-amplitude group is register-resident.
template<int L>
__device__ __forceinline__ void quad_pass(
    float2* __restrict__ st, int tid,
    const unsigned* __restrict__ PS,
    const float* __restrict__ CC, const float* __restrict__ SS)
{
    const int g    = tid;                     // TPB == DIM/16 groups
    const int base = g << 4;
    const int sb   = base + g;                // == SLOT(base); +v stays in-block
    float2 z[16];
    #pragma unroll
    for (int v = 0; v < 16; ++v) z[v] = st[sb + v];
    // fold the (nibble-free) base parity into the sine sign
    float sA = (__popc(base & (int)PS[10]) & 1) ? -SS[10] : SS[10];
    float sB = (__popc(base & (int)PS[11]) & 1) ? -SS[11] : SS[11];
    float sC = (__popc(base & (int)PS[12]) & 1) ? -SS[12] : SS[12];
    float sD = (__popc(base & (int)PS[13]) & 1) ? -SS[13] : SS[13];
    rot16<QM[L][0], QPN[L][0]>(z, CC[10], sA);
    rot16<QM[L][1], QPN[L][1]>(z, CC[11], sB);
    rot16<QM[L][2], QPN[L][2]>(z, CC[12], sC);
    rot16<QM[L][3], QPN[L][3]>(z, CC[13], sD);
    #pragma unroll
    for (int v = 0; v < 16; ++v) st[sb + v] = z[v];
    __syncthreads();
}

__global__ void __launch_bounds__(TPB, 1)
vqc_kernel(const float* __restrict__ x, const float* __restrict__ fs,
           const float* __restrict__ vp, float* __restrict__ out)
{
    extern __shared__ float2 st[];            // SMEM_SLOTS (skewed)
    __shared__ float2 V0[NQ], V1[NQ];         // per-wire encoding 2-vectors
    __shared__ float2 TA[128], TB[128];       // subset-product tables (hi/lo 7 wires)
    __shared__ float CCa[NL][NQ], SSa[NL][NQ];
    __shared__ unsigned MSa[NL][NQ], PSa[NL][NQ];
    __shared__ float red[TPB / 32];

    const int tid = threadIdx.x;
    const int b   = blockIdx.x;

    // ---- setup ----
    if (tid < NQ) {
        float xi = x[b * NQ + tid];
        float s, c, sf, cf;
        sincosf(0.5f * xi, &s, &c);
        sincosf(0.5f * fs[tid] * xi, &sf, &cf);
        const float r = 0.70710678118654752440f;
        float pa = (c - s) * r;               // RY(x)H|0>
        float pb = (c + s) * r;
        V0[tid] = make_float2(cf * pa, -sf * pb);   // RX on top
        V1[tid] = make_float2(cf * pb, -sf * pa);
    } else if (tid >= 32 && tid < 32 + NL * NQ) {
        int k = tid - 32, l = k / NQ, w = k % NQ;
        float s, c;
        sincosf(0.5f * vp[l * NQ + w], &s, &c);
        CCa[l][w] = c; SSa[l][w] = s;
    } else if (tid == 128) {
        // sigma tracking: m_w = column w of (L^-1)^k, p_w = row w of L^k
        unsigned m[NQ], p[NQ];
        for (int w = 0; w < NQ; ++w) m[w] = p[w] = 1u << (13 - w);
        for (int l = 0; l < NL; ++l) {
            for (int i = 0; i < NQ - 1; ++i) m[i] ^= m[i + 1];
            for (int i = 0; i < NQ - 1; ++i) p[i + 1] ^= p[i];
            for (int w = 0; w < NQ; ++w) { MSa[l][w] = m[w]; PSa[l][w] = p[w]; }
        }
    }
    __syncthreads();

    // ---- subset-product tables ----
    if (tid < 128) {
        float2 acc = make_float2(1.0f, 0.0f);
        #pragma unroll
        for (int i = 7; i < 14; ++i) {
            int bit = (tid >> (13 - i)) & 1;
            acc = cmul(acc, bit ? V1[i] : V0[i]);
        }
        TB[tid] = acc;
    } else if (tid < 256) {
        int h = tid - 128;
        float2 acc = make_float2(1.0f, 0.0f);
        #pragma unroll
        for (int i = 0; i < 7; ++i) {
            int bit = (h >> (6 - i)) & 1;
            acc = cmul(acc, bit ? V1[i] : V0[i]);
        }
        TA[h] = acc;
    }
    __syncthreads();

    // ---- fill encoded product state ----
    #pragma unroll
    for (int it = 0; it < DIM / TPB; ++it) {
        int t = tid + it * TPB;
        st[SLOT(t)] = cmul(TA[t >> 7], TB[t & 127]);
    }
    __syncthreads();

    // ---- variational layers (ladder tracked, never materialized) ----
    #pragma unroll 1
    for (int l = 0; l < NL; ++l) {
        two_wire_passes(st, tid, MSa[l], PSa[l], CCa[l], SSa[l]);
        switch (l) {
            case 0: quad_pass<0>(st, tid, PSa[0], CCa[0], SSa[0]); break;
            case 1: quad_pass<1>(st, tid, PSa[1], CCa[1], SSa[1]); break;
            case 2: quad_pass<2>(st, tid, PSa[2], CCa[2], SSa[2]); break;
            case 3: quad_pass<3>(st, tid, PSa[3], CCa[3], SSa[3]); break;
            case 4: quad_pass<4>(st, tid, PSa[4], CCa[4], SSa[4]); break;
            case 5: quad_pass<5>(st, tid, PSa[5], CCa[5], SSa[5]); break;
        }
    }

    // ---- <Z_0>: p_0 is ladder-invariant = bit 13 of physical index ----
    float acc = 0.0f;
    #pragma unroll
    for (int it = 0; it < DIM / TPB; ++it) {
        int t = tid + it * TPB;
        float2 a = st[SLOT(t)];
        float pr = fmaf(a.x, a.x, a.y * a.y);
        acc += (t & (1 << 13)) ? -pr : pr;
    }
    #pragma unroll
    for (int o = 16; o > 0; o >>= 1) acc += __shfl_xor_sync(0xffffffffu, acc, o);
    if ((tid & 31) == 0) red[tid >> 5] = acc;
    __syncthreads();
    if (tid < 32) {
        float v = (tid < TPB / 32) ? red[tid] : 0.0f;
        #pragma unroll
        for (int o = 16; o > 0; o >>= 1) v += __shfl_xor_sync(0xffffffffu, v, o);
        if (tid == 0) out[b] = v;
    }
}

} // namespace

extern "C" void kernel_launch(void* const* d_in, const int* in_sizes, int n_in,
                              void* d_out, int out_size)
{
    const float* x  = (const float*)d_in[0];   // [B, 14]
    const float* fs = (const float*)d_in[1];   // [14]
    const float* vp = (const float*)d_in[2];   // [6, 14]
    float* out = (float*)d_out;                // [B, 1] float32

    const int B = in_sizes[0] / NQ;
    const size_t smem = (size_t)SMEM_SLOTS * sizeof(float2);   // 136 KB
    cudaFuncSetAttribute(vqc_kernel, cudaFuncAttributeMaxDynamicSharedMemorySize,
                         (int)smem);
    vqc_kernel<<<B, TPB, smem>>>(x, fs, vp, out);
}

// round 4
// speedup vs baseline: 1.3625x; 1.3625x over previous
#include <cuda_runtime.h>

namespace {

constexpr int NQ  = 14;
constexpr int DIM = 1 << NQ;                  // 16384 amplitudes
constexpr int TPB = 512;
constexpr int NL  = 6;
constexpr int SMEM_SLOTS = DIM + 3 * (DIM / 16);   // skew-3 layout: 19456 slots

using u64 = unsigned long long;

// Skewed slot: conflict-free for (a) lanes varying in low-5 index bits via XOR
// and (b) per-thread 16-consecutive blocks (slot stride 19 -> bank stride
// 6 mod 32, distinct within a 16-lane phase).
__device__ __forceinline__ int SLOT(int t) { return t + 3 * (t >> 4); }

// ---- packed f32x2 helpers (Blackwell FFMA2 path) ----
__device__ __forceinline__ u64 pk2(float lo, float hi) {
    u64 r; asm("mov.b64 %0, {%1, %2};" : "=l"(r) : "f"(lo), "f"(hi)); return r;
}
__device__ __forceinline__ void up2(u64 v, float& lo, float& hi) {
    asm("mov.b64 {%0, %1}, %2;" : "=f"(lo), "=f"(hi) : "l"(v));
}
__device__ __forceinline__ u64 ffma2(u64 a, u64 b, u64 c) {
    u64 d; asm("fma.rn.f32x2 %0, %1, %2, %3;" : "=l"(d) : "l"(a), "l"(b), "l"(c)); return d;
}
__device__ __forceinline__ u64 fmul2(u64 a, u64 b) {
    u64 d; asm("mul.rn.f32x2 %0, %1, %2;" : "=l"(d) : "l"(a), "l"(b)); return d;
}

__device__ __forceinline__ float2 cmulf(float2 a, float2 b) {
    return make_float2(fmaf(a.x, b.x, -a.y * b.y), fmaf(a.x, b.y, a.y * b.x));
}

// K-wire rotation on an unscrambled coset held in registers.
// Because p_i . m_j = delta_ij, the sign of wire j is constant over the coset
// (parity(t & p_j)); the rotation is then a pure hypercube butterfly on bit j.
template<int K>
__device__ __forceinline__ void rotk(u64* z, const float* cc, const float* ss,
                                     const unsigned* pp, int t) {
    #pragma unroll
    for (int j = 0; j < K; ++j) {
        float se = (__popc(t & (int)pp[j]) & 1) ? -ss[j] : ss[j];
        u64 C  = pk2(cc[j], cc[j]);
        u64 S  = pk2(se, se);
        u64 NS = pk2(-se, -se);
        #pragma unroll
        for (int v = 0; v < (1 << K); ++v) {
            if (!(v & (1 << j))) {
                u64 a = z[v], b = z[v | (1 << j)];
                z[v]            = ffma2(C, a, fmul2(NS, b));   // A' = cA - sB
                z[v | (1 << j)] = ffma2(C, b, fmul2(S,  a));   // B' = sA + cB
            }
        }
    }
}

__global__ void __launch_bounds__(TPB, 1)
vqc_kernel(const float* __restrict__ x, const float* __restrict__ fs,
           const float* __restrict__ vp, float* __restrict__ out)
{
    extern __shared__ u64 stq[];                 // SMEM_SLOTS skewed amplitudes
    __shared__ float2 V0[NQ], V1[NQ];            // per-wire encoding 2-vectors
    __shared__ float2 TA[128], TB[128];          // subset-product tables
    __shared__ float CCa[NL][NQ], SSa[NL][NQ];   // cos/sin(vp/2)
    __shared__ unsigned MSa[NL][NQ], PSa[NL][NQ];// tracked masks / parity rows
    __shared__ int XMA[NL][32], XMB[NL][32], XMC[NL][16];  // coset XOR tables
    __shared__ float red[TPB / 32];

    const int tid = threadIdx.x;
    const int b   = blockIdx.x;

    // ---- stage 1: encoding vectors, rotation params, ladder tracking ----
    if (tid < NQ) {
        float xi = x[b * NQ + tid];
        float s, c, sf, cf;
        sincosf(0.5f * xi, &s, &c);
        sincosf(0.5f * fs[tid] * xi, &sf, &cf);
        const float r = 0.70710678118654752440f;
        float pa = (c - s) * r;                  // RY(x) H |0>
        float pb = (c + s) * r;
        V0[tid] = make_float2(cf * pa, -sf * pb);   // RX(fs*x) applied on top
        V1[tid] = make_float2(cf * pb, -sf * pa);
    } else if (tid >= 32 && tid < 32 + NL * NQ) {
        int k = tid - 32, l = k / NQ, w = k % NQ;
        float s, c;
        sincosf(0.5f * vp[l * NQ + w], &s, &c);
        CCa[l][w] = c; SSa[l][w] = s;
    } else if (tid == 128) {
        // m_w = column w of (L^-1)^k, p_w = row w of L^k ; p_i . m_j = delta_ij
        unsigned m[NQ], p[NQ];
        for (int w = 0; w < NQ; ++w) m[w] = p[w] = 1u << (13 - w);
        for (int l = 0; l < NL; ++l) {
            for (int i = 0; i < NQ - 1; ++i) m[i] ^= m[i + 1];
            for (int i = 0; i < NQ - 1; ++i) p[i + 1] ^= p[i];
            for (int w = 0; w < NQ; ++w) { MSa[l][w] = m[w]; PSa[l][w] = p[w]; }
        }
    }
    __syncthreads();

    // ---- stage 2: product tables + coset XOR tables ----
    if (tid < 128) {
        float2 acc = make_float2(1.0f, 0.0f);
        #pragma unroll
        for (int i = 7; i < 14; ++i) {
            int bit = (tid >> (13 - i)) & 1;
            acc = cmulf(acc, bit ? V1[i] : V0[i]);
        }
        TB[tid] = acc;
    } else if (tid < 256) {
        int h = tid - 128;
        float2 acc = make_float2(1.0f, 0.0f);
        #pragma unroll
        for (int i = 0; i < 7; ++i) {
            int bit = (h >> (6 - i)) & 1;
            acc = cmulf(acc, bit ? V1[i] : V0[i]);
        }
        TA[h] = acc;
    }
    if (tid < 192) {                       // XMA: wires 0..4
        int l = tid >> 5, v = tid & 31, m = 0;
        #pragma unroll
        for (int j = 0; j < 5; ++j) if ((v >> j) & 1) m ^= (int)MSa[l][j];
        XMA[l][v] = m;
    } else if (tid < 384) {                // XMB: wires 5..9
        int k = tid - 192, l = k >> 5, v = k & 31, m = 0;
        #pragma unroll
        for (int j = 0; j < 5; ++j) if ((v >> j) & 1) m ^= (int)MSa[l][5 + j];
        XMB[l][v] = m;
    } else if (tid < 480) {                // XMC: wires 10..13 (masks in low nibble)
        int k = tid - 384, l = k >> 4, v = k & 15, m = 0;
        #pragma unroll
        for (int j = 0; j < 4; ++j) if ((v >> j) & 1) m ^= (int)MSa[l][10 + j];
        XMC[l][v] = m;
    }
    __syncthreads();

    float acc = 0.0f;

    #pragma unroll 1
    for (int l = 0; l < NL; ++l) {
        const float*    cc = CCa[l];
        const float*    ss = SSa[l];
        const unsigned* pp = PSa[l];

        // ---- pass A: wires 0..4 (pivot bits 13..9), t = tid in 0..511 ----
        {
            const int t  = tid;
            const int* xm = XMA[l];
            u64 z[32];
            if (l == 0) {
                // generate the encoded product state directly (fill fused)
                #pragma unroll
                for (int v = 0; v < 32; ++v) {
                    int u = t ^ xm[v];
                    float2 r = cmulf(TA[u >> 7], TB[u & 127]);
                    z[v] = pk2(r.x, r.y);
                }
            } else {
                #pragma unroll
                for (int v = 0; v < 32; ++v) z[v] = stq[SLOT(t ^ xm[v])];
            }
            rotk<5>(z, cc + 0, ss + 0, pp + 0, t);
            #pragma unroll
            for (int v = 0; v < 32; ++v) stq[SLOT(t ^ xm[v])] = z[v];
        }
        __syncthreads();

        // ---- pass B: wires 5..9 (pivot bits 8..4), t free bits {0..3,9..13} ----
        {
            const int t  = ((tid >> 4) << 9) | (tid & 15);
            const int* xm = XMB[l];
            u64 z[32];
            #pragma unroll
            for (int v = 0; v < 32; ++v) z[v] = stq[SLOT(t ^ xm[v])];
            rotk<5>(z, cc + 5, ss + 5, pp + 5, t);
            #pragma unroll
            for (int v = 0; v < 32; ++v) stq[SLOT(t ^ xm[v])] = z[v];
        }
        __syncthreads();

        // ---- pass C: wires 10..13 (masks in low nibble): 16-consecutive tiles ----
        #pragma unroll 1
        for (int it = 0; it < 2; ++it) {
            const int g  = tid + it * TPB;          // 1024 tiles
            const int t  = g << 4;
            const int sb = SLOT(t);                 // = 19*g ; +x stays in-tile
            const int* xm = XMC[l];
            u64 z[16];
            #pragma unroll
            for (int v = 0; v < 16; ++v) z[v] = stq[sb + xm[v]];
            rotk<4>(z, cc + 10, ss + 10, pp + 10, t);
            if (l == NL - 1) {
                // readout fused: <Z_0> sign = bit13 of physical index (p_0 invariant)
                float ssum = 0.0f;
                #pragma unroll
                for (int v = 0; v < 16; ++v) {
                    float zx, zy; up2(z[v], zx, zy);
                    ssum = fmaf(zx, zx, fmaf(zy, zy, ssum));
                }
                acc += ((g >> 9) & 1) ? -ssum : ssum;
            } else {
                #pragma unroll
                for (int v = 0; v < 16; ++v) stq[sb + xm[v]] = z[v];
            }
        }
        if (l != NL - 1) __syncthreads();
    }

    // ---- block reduction ----
    #pragma unroll
    for (int o = 16; o > 0; o >>= 1) acc += __shfl_xor_sync(0xffffffffu, acc, o);
    if ((tid & 31) == 0) red[tid >> 5] = acc;
    __syncthreads();
    if (tid < 32) {
        float v = (tid < TPB / 32) ? red[tid] : 0.0f;
        #pragma unroll
        for (int o = 16; o > 0; o >>= 1) v += __shfl_xor_sync(0xffffffffu, v, o);
        if (tid == 0) out[b] = v;
    }
}

} // namespace

extern "C" void kernel_launch(void* const* d_in, const int* in_sizes, int n_in,
                              void* d_out, int out_size)
{
    const float* x  = (const float*)d_in[0];   // [B, 14]
    const float* fs = (const float*)d_in[1];   // [14]
    const float* vp = (const float*)d_in[2];   // [6, 14]
    float* out = (float*)d_out;                // [B, 1] float32

    const int B = in_sizes[0] / NQ;
    const size_t smem = (size_t)SMEM_SLOTS * sizeof(u64);   // ~152 KB
    cudaFuncSetAttribute(vqc_kernel, cudaFuncAttributeMaxDynamicSharedMemorySize,
                         (int)smem);
    vqc_kernel<<<B, TPB, smem>>>(x, fs, vp, out);
}

// round 9
// speedup vs baseline: 1.4972x; 1.0989x over previous
#include <cuda_runtime.h>

namespace {

constexpr int NQ  = 14;
constexpr int DIM = 1 << NQ;          // 16384 amplitudes
constexpr int TPB = 512;
constexpr int NL  = 6;

// Low-nibble pairing masks (QM) and parity-row nibbles (QPN) for wires 10..13
// at layer L (k = L+1 ladders applied), as constexpr accessor functions so
// device code can use them without --expt-relaxed-constexpr.
__host__ __device__ constexpr int QMf(int L, int J) {
    const int t[6][4] = {{12,6,3,1},{10,5,2,1},{15,7,3,1},{8,4,2,1},{12,6,3,1},{10,5,2,1}};
    return t[L][J];
}
__host__ __device__ constexpr int QPNf(int L, int J) {
    const int t[6][4] = {{8,12,14,15},{8,4,10,5},{8,12,6,3},{8,4,2,1},{8,12,14,15},{8,4,10,5}};
    return t[L][J];
}
__host__ __device__ constexpr int par4(int x) {
    return ((x >> 3) ^ (x >> 2) ^ (x >> 1) ^ x) & 1;
}

using u64 = unsigned long long;

// GF(2)-linear involutive swizzle: conflict-free (per half-warp, the LDS.64
// service granularity) for all three pass access patterns.
__device__ __forceinline__ int SW(int t) { return t ^ ((t >> 4) & 15) ^ ((t >> 8) & 15); }

// ---- packed f32x2 helpers ----
__device__ __forceinline__ u64 pk2(float lo, float hi) {
    u64 r; asm("mov.b64 %0, {%1, %2};" : "=l"(r) : "f"(lo), "f"(hi)); return r;
}
__device__ __forceinline__ void up2(u64 v, float& lo, float& hi) {
    asm("mov.b64 {%0, %1}, %2;" : "=f"(lo), "=f"(hi) : "l"(v));
}
__device__ __forceinline__ u64 ffma2(u64 a, u64 b, u64 c) {
    u64 d; asm("fma.rn.f32x2 %0, %1, %2, %3;" : "=l"(d) : "l"(a), "l"(b), "l"(c)); return d;
}
__device__ __forceinline__ float xsgn(float v, unsigned flip) {
    return __uint_as_float(__float_as_uint(v) ^ flip);
}
__device__ __forceinline__ float2 cmulf(float2 a, float2 b) {
    return make_float2(fmaf(a.x, b.x, -a.y * b.y), fmaf(a.x, b.y, a.y * b.x));
}

// Lifting (3-shear) rotation on a pair: [[c,-s],[s,c]] with u=(c-1)/s.
// a' = a + u b ; b' = b + s a' ; a'' = a' + u b'.
__device__ __forceinline__ void liftp(u64& a, u64& b, u64 U, u64 S) {
    a = ffma2(U, b, a);
    b = ffma2(S, a, b);
    a = ffma2(U, b, a);
}

// K-wire rotation on an unscrambled coset (p_i.m_j = delta_ij => sign of each
// wire is constant over the coset: one popc per wire).
template<int K>
__device__ __forceinline__ void rotk(u64* z, const float* uu, const float* ss,
                                     const unsigned* pp, int t) {
    #pragma unroll
    for (int j = 0; j < K; ++j) {
        unsigned fl = (__popc(t & (int)pp[j]) & 1u) << 31;
        float ue = xsgn(uu[j], fl), se = xsgn(ss[j], fl);
        u64 U = pk2(ue, ue), S = pk2(se, se);
        #pragma unroll
        for (int v = 0; v < (1 << K); ++v)
            if (!(v & (1 << j)))
                liftp(z[v], z[v | (1 << j)], U, S);
    }
}

// Pass C: wires 10..13, masks confined to the low nibble (compile-time).
// Tile g holds physical indices 16g+v at slots (16g|kg)^v, kg = (g&15)^((g>>4)&15).
template<int L, bool LAST>
__device__ __forceinline__ float passC(u64* __restrict__ stq, int g,
                                       const float* uu, const float* ss,
                                       const unsigned* pp) {
    const int kg = (g & 15) ^ ((g >> 4) & 15);
    const int sb = (g << 4) | kg;
    u64 z[16];
    #pragma unroll
    for (int v = 0; v < 16; ++v) z[v] = stq[sb ^ v];
    #pragma unroll
    for (int j = 0; j < 4; ++j) {
        const int M = QMf(L, j), PN = QPNf(L, j);
        const int PIV = M & (-M);
        unsigned fl = (__popc((g << 4) & (int)pp[j]) & 1u) << 31;
        float ue = xsgn(uu[j], fl), se = xsgn(ss[j], fl);
        u64 U  = pk2(ue, ue),   S  = pk2(se, se);
        u64 Un = pk2(-ue, -ue), Sn = pk2(-se, -se);
        #pragma unroll
        for (int v = 0; v < 16; ++v) {
            if (!(v & PIV)) {
                if (par4(v & PN)) liftp(z[v], z[v ^ M], Un, Sn);
                else              liftp(z[v], z[v ^ M], U,  S);
            }
        }
    }
    if (LAST) {
        // <Z_0>: p_0 ladder-invariant => sign = bit13 of physical index = g bit9
        float ssum = 0.0f;
        #pragma unroll
        for (int v = 0; v < 16; ++v) {
            float zx, zy; up2(z[v], zx, zy);
            ssum = fmaf(zx, zx, fmaf(zy, zy, ssum));
        }
        return ((g >> 9) & 1) ? -ssum : ssum;
    } else {
        #pragma unroll
        for (int v = 0; v < 16; ++v) stq[sb ^ v] = z[v];
        return 0.0f;
    }
}

__global__ void __launch_bounds__(TPB, 1)
vqc_kernel(const float* __restrict__ x, const float* __restrict__ fs,
           const float* __restrict__ vp, float* __restrict__ out)
{
    extern __shared__ u64 stq[];                 // DIM swizzled amplitudes (128 KB)
    __shared__ float2 V0[NQ], V1[NQ];            // per-wire encoding 2-vectors
    __shared__ float2 TA[128], TB[128];          // subset-product tables
    __shared__ float UUa[NL][NQ], SSa[NL][NQ];   // lifting consts u=(c-1)/s, s
    __shared__ unsigned MSa[NL][NQ], PSa[NL][NQ];// tracked masks / parity rows
    __shared__ int XMA[NL][32], XMB[NL][32];     // sw(coset XOR) tables
    __shared__ int XMA0[32];                     // raw coset XORs, layer 0 (fill)
    __shared__ float red[TPB / 32];

    const int tid = threadIdx.x;
    const int b   = blockIdx.x;

    // ---- stage 1: encoding vectors, lifting params, ladder tracking ----
    if (tid < NQ) {
        float xi = x[b * NQ + tid];
        float s, c, sf, cf;
        sincosf(0.5f * xi, &s, &c);
        sincosf(0.5f * fs[tid] * xi, &sf, &cf);
        const float r = 0.70710678118654752440f;
        float pa = (c - s) * r;                  // RY(x) H |0>
        float pb = (c + s) * r;
        V0[tid] = make_float2(cf * pa, -sf * pb);   // RX(fs*x) applied on top
        V1[tid] = make_float2(cf * pb, -sf * pa);
    } else if (tid >= 32 && tid < 32 + NL * NQ) {
        int k = tid - 32, l = k / NQ, w = k % NQ;
        float s, c;
        sincosf(0.5f * vp[l * NQ + w], &s, &c);
        SSa[l][w] = s;
        UUa[l][w] = (s == 0.0f) ? 0.0f : (c - 1.0f) / s;   // = -tan(phi/2)
    } else if (tid == 128) {
        // m_w = column w of (L^-1)^k, p_w = row w of L^k ; p_i . m_j = delta_ij
        unsigned m[NQ], p[NQ];
        for (int w = 0; w < NQ; ++w) m[w] = p[w] = 1u << (13 - w);
        for (int l = 0; l < NL; ++l) {
            for (int i = 0; i < NQ - 1; ++i) m[i] ^= m[i + 1];
            for (int i = 0; i < NQ - 1; ++i) p[i + 1] ^= p[i];
            for (int w = 0; w < NQ; ++w) { MSa[l][w] = m[w]; PSa[l][w] = p[w]; }
        }
    }
    __syncthreads();

    // ---- stage 2: product tables + swizzled coset-XOR tables ----
    if (tid < 128) {
        float2 acc = make_float2(1.0f, 0.0f);
        #pragma unroll
        for (int i = 7; i < 14; ++i) {
            int bit = (tid >> (13 - i)) & 1;
            acc = cmulf(acc, bit ? V1[i] : V0[i]);
        }
        TB[tid] = acc;
    } else if (tid < 256) {
        int h = tid - 128;
        float2 acc = make_float2(1.0f, 0.0f);
        #pragma unroll
        for (int i = 0; i < 7; ++i) {
            int bit = (h >> (6 - i)) & 1;
            acc = cmulf(acc, bit ? V1[i] : V0[i]);
        }
        TA[h] = acc;
    }
    if (tid < 192) {                       // XMA: wires 0..4
        int l = tid >> 5, v = tid & 31, m = 0;
        #pragma unroll
        for (int j = 0; j < 5; ++j) if ((v >> j) & 1) m ^= (int)MSa[l][j];
        XMA[l][v] = SW(m);                 // sw is GF(2)-linear: fold it here
        if (l == 0) XMA0[v] = m;
    } else if (tid < 384) {                // XMB: wires 5..9
        int k = tid - 192, l = k >> 5, v = k & 31, m = 0;
        #pragma unroll
        for (int j = 0; j < 5; ++j) if ((v >> j) & 1) m ^= (int)MSa[l][5 + j];
        XMB[l][v] = SW(m);
    }
    __syncthreads();

    float acc = 0.0f;

    #pragma unroll 1
    for (int l = 0; l < NL; ++l) {
        const float*    uu = UUa[l];
        const float*    ss = SSa[l];
        const unsigned* pp = PSa[l];

        // ---- pass A: wires 0..4 (pivot bits 13..9), coset rep t = tid ----
        {
            const int t   = tid;
            const int swt = SW(t);
            const int* xm = XMA[l];
            u64 z[32];
            if (l == 0) {
                #pragma unroll
                for (int v = 0; v < 32; ++v) {
                    int u = t ^ XMA0[v];
                    float2 r = cmulf(TA[u >> 7], TB[u & 127]);
                    z[v] = pk2(r.x, r.y);
                }
            } else {
                #pragma unroll
                for (int v = 0; v < 32; ++v) z[v] = stq[swt ^ xm[v]];
            }
            rotk<5>(z, uu + 0, ss + 0, pp + 0, t);
            #pragma unroll
            for (int v = 0; v < 32; ++v) stq[swt ^ xm[v]] = z[v];
        }
        __syncthreads();

        // ---- pass B: wires 5..9 (pivot bits 8..4), free bits {0..3,9..13} ----
        {
            const int t   = ((tid >> 4) << 9) | (tid & 15);
            const int swt = SW(t);
            const int* xm = XMB[l];
            u64 z[32];
            #pragma unroll
            for (int v = 0; v < 32; ++v) z[v] = stq[swt ^ xm[v]];
            rotk<5>(z, uu + 5, ss + 5, pp + 5, t);
            #pragma unroll
            for (int v = 0; v < 32; ++v) stq[swt ^ xm[v]] = z[v];
        }
        __syncthreads();

        // ---- pass C: wires 10..13, 16-amp register tiles ----
        switch (l) {
            case 0:
                acc += passC<0,false>(stq, tid,       uu+10, ss+10, pp+10);
                acc += passC<0,false>(stq, tid + TPB, uu+10, ss+10, pp+10);
                break;
            case 1:
                acc += passC<1,false>(stq, tid,       uu+10, ss+10, pp+10);
                acc += passC<1,false>(stq, tid + TPB, uu+10, ss+10, pp+10);
                break;
            case 2:
                acc += passC<2,false>(stq, tid,       uu+10, ss+10, pp+10);
                acc += passC<2,false>(stq, tid + TPB, uu+10, ss+10, pp+10);
                break;
            case 3:
                acc += passC<3,false>(stq, tid,       uu+10, ss+10, pp+10);
                acc += passC<3,false>(stq, tid + TPB, uu+10, ss+10, pp+10);
                break;
            case 4:
                acc += passC<4,false>(stq, tid,       uu+10, ss+10, pp+10);
                acc += passC<4,false>(stq, tid + TPB, uu+10, ss+10, pp+10);
                break;
            case 5:
                acc += passC<5,true >(stq, tid,       uu+10, ss+10, pp+10);
                acc += passC<5,true >(stq, tid + TPB, uu+10, ss+10, pp+10);
                break;
        }
        if (l != NL - 1) __syncthreads();
    }

    // ---- block reduction ----
    #pragma unroll
    for (int o = 16; o > 0; o >>= 1) acc += __shfl_xor_sync(0xffffffffu, acc, o);
    if ((tid & 31) == 0) red[tid >> 5] = acc;
    __syncthreads();
    if (tid < 32) {
        float v = (tid < TPB / 32) ? red[tid] : 0.0f;
        #pragma unroll
        for (int o = 16; o > 0; o >>= 1) v += __shfl_xor_sync(0xffffffffu, v, o);
        if (tid == 0) out[b] = v;
    }
}

} // namespace

extern "C" void kernel_launch(void* const* d_in, const int* in_sizes, int n_in,
                              void* d_out, int out_size)
{
    const float* x  = (const float*)d_in[0];   // [B, 14]
    const float* fs = (const float*)d_in[1];   // [14]
    const float* vp = (const float*)d_in[2];   // [6, 14]
    float* out = (float*)d_out;                // [B, 1] float32

    const int B = in_sizes[0] / NQ;
    const size_t smem = (size_t)DIM * sizeof(u64);   // 128 KB dynamic
    cudaFuncSetAttribute(vqc_kernel, cudaFuncAttributeMaxDynamicSharedMemorySize,
                         (int)smem);
    vqc_kernel<<<B, TPB, smem>>>(x, fs, vp, out);
}

// round 10
// speedup vs baseline: 1.5497x; 1.0350x over previous
#include <cuda_runtime.h>

namespace {

constexpr int NQ  = 14;
constexpr int DIM = 1 << NQ;          // 16384 amplitudes
constexpr int TPB = 512;
constexpr int NL  = 6;

using u64 = unsigned long long;

// GF(2)-linear involutive bank swizzle (conflict-free per half-warp for all
// access patterns used below) and the ladder permutation h(t) = t ^ (t>>1)
// (psi_after_ladder(t) = psi_before(h(t)); prefix-parity over wires).
__device__   __forceinline__ int SW (int t) { return t ^ ((t >> 4) & 15) ^ ((t >> 8) & 15); }
__host__ __device__ constexpr int SWc(int t) { return t ^ ((t >> 4) & 15) ^ ((t >> 8) & 15); }
__host__ __device__ constexpr int Hc (int t) { return t ^ (t >> 1); }

// ---- packed f32x2 helpers ----
__device__ __forceinline__ u64 pk2(float lo, float hi) {
    u64 r; asm("mov.b64 %0, {%1, %2};" : "=l"(r) : "f"(lo), "f"(hi)); return r;
}
__device__ __forceinline__ void up2(u64 v, float& lo, float& hi) {
    asm("mov.b64 {%0, %1}, %2;" : "=f"(lo), "=f"(hi) : "l"(v));
}
__device__ __forceinline__ u64 ffma2(u64 a, u64 b, u64 c) {
    u64 d; asm("fma.rn.f32x2 %0, %1, %2, %3;" : "=l"(d) : "l"(a), "l"(b), "l"(c)); return d;
}
__device__ __forceinline__ u64 fmul2(u64 a, u64 b) {
    u64 d; asm("mul.rn.f32x2 %0, %1, %2;" : "=l"(d) : "l"(a), "l"(b)); return d;
}
__device__ __forceinline__ float2 cmulf(float2 a, float2 b) {
    return make_float2(fmaf(a.x, b.x, -a.y * b.y), fmaf(a.x, b.y, a.y * b.x));
}

// Lifting (3-shear) RY on a pair (a = logical-0 side, no sign games needed
// after ladder materialization): a += u b ; b += s a ; a += u b.
__device__ __forceinline__ void liftp(u64& a, u64& b, u64 U, u64 S) {
    a = ffma2(U, b, a);
    b = ffma2(S, a, b);
    a = ffma2(U, b, a);
}

__global__ void __launch_bounds__(TPB, 1)
vqc_kernel(const float* __restrict__ x, const float* __restrict__ fs,
           const float* __restrict__ vp, float* __restrict__ out)
{
    extern __shared__ u64 stq[];               // DIM swizzled amplitudes (128 KB)
    __shared__ float2 V0[NQ], V1[NQ];          // per-wire encoding 2-vectors
    __shared__ float2 TA[128], TB[128];        // subset-product tables
    __shared__ float UUa[NL][NQ], SSa[NL][NQ], CCa[NL][NQ];
    __shared__ float red[TPB / 32];

    const int tid = threadIdx.x;
    const int b   = blockIdx.x;

    // ---- stage 1: encoding vectors + rotation constants ----
    if (tid < NQ) {
        float xi = x[b * NQ + tid];
        float s, c, sf, cf;
        sincosf(0.5f * xi, &s, &c);
        sincosf(0.5f * fs[tid] * xi, &sf, &cf);
        const float r = 0.70710678118654752440f;
        float pa = (c - s) * r;                // RY(x) H |0>
        float pb = (c + s) * r;
        V0[tid] = make_float2(cf * pa, -sf * pb);   // RX(fs*x) applied on top
        V1[tid] = make_float2(cf * pb, -sf * pa);
    } else if (tid >= 32 && tid < 32 + NL * NQ) {
        int k = tid - 32, l = k / NQ, w = k % NQ;
        float s, c;
        sincosf(0.5f * vp[l * NQ + w], &s, &c);
        SSa[l][w] = s;
        CCa[l][w] = c;
        UUa[l][w] = (s == 0.0f) ? 0.0f : (c - 1.0f) / s;   // = -tan(phi/2)
    }
    __syncthreads();

    // ---- stage 2: subset-product tables ----
    if (tid < 128) {
        float2 acc = make_float2(1.0f, 0.0f);
        #pragma unroll
        for (int i = 7; i < 14; ++i) {
            int bit = (tid >> (13 - i)) & 1;
            acc = cmulf(acc, bit ? V1[i] : V0[i]);
        }
        TB[tid] = acc;
    } else if (tid < 256) {
        int h = tid - 128;
        float2 acc = make_float2(1.0f, 0.0f);
        #pragma unroll
        for (int i = 0; i < 7; ++i) {
            int bit = (h >> (6 - i)) & 1;
            acc = cmulf(acc, bit ? V1[i] : V0[i]);
        }
        TA[h] = acc;
    }
    __syncthreads();

    float acc = 0.0f;
    u64 z[32];

    #pragma unroll 1
    for (int l = 0; l < NL; ++l) {
        // ================= pass A: wires 0..4 (bits 13..9) =================
        // amp index u = (v<<9) | tid.  Load applies the ladder: z(u)=st(h(u)).
        // h and SW are GF(2)-linear -> addr = SW(h(tid)) ^ SWc(h(v<<9)).
        if (l == 0) {
            const int hr = Hc(tid);
            #pragma unroll
            for (int v = 0; v < 32; ++v) {
                int idx = hr ^ Hc(v << 9);     // encoded product state, ladder-mapped
                float2 a = cmulf(TA[idx >> 7], TB[idx & 127]);
                z[v] = pk2(a.x, a.y);
            }
        } else {
            const int la = SW(Hc(tid));
            #pragma unroll
            for (int v = 0; v < 32; ++v) z[v] = stq[la ^ SWc(Hc(v << 9))];
        }
        // rotate wires 0..4: reg bit jj <-> wire (4-jj); plain lifting, no signs
        #pragma unroll
        for (int jj = 0; jj < 5; ++jj) {
            const int w = 4 - jj;
            u64 U2 = pk2(UUa[l][w], UUa[l][w]);
            u64 S2 = pk2(SSa[l][w], SSa[l][w]);
            #pragma unroll
            for (int v = 0; v < 32; ++v)
                if (!(v & (1 << jj)))
                    liftp(z[v], z[v | (1 << jj)], U2, S2);
        }
        // h-gather crosses tiles: drain all loads before in-place stores
        if (l != 0) __syncthreads();
        {
            const int sa = SW(tid);
            #pragma unroll
            for (int v = 0; v < 32; ++v) stq[sa ^ SWc(v << 9)] = z[v];
        }
        __syncthreads();

        // ============ pass BC: wires 5..9 (regs) + 10..13 (lanes) ============
        // amp index u = (w5<<9) | (v<<4) | l4 ; w5 = tid>>4, l4 = tid&15.
        const int l4 = tid & 15;
        const int sb = SW((tid >> 4) << 9) ^ SW(l4);
        #pragma unroll
        for (int v = 0; v < 32; ++v) z[v] = stq[sb ^ SWc(v << 4)];
        // wires 5..9: reg bit jj <-> wire (9-jj), in-register lifting
        #pragma unroll
        for (int jj = 0; jj < 5; ++jj) {
            const int w = 9 - jj;
            u64 U2 = pk2(UUa[l][w], UUa[l][w]);
            u64 S2 = pk2(SSa[l][w], SSa[l][w]);
            #pragma unroll
            for (int v = 0; v < 32; ++v)
                if (!(v & (1 << jj)))
                    liftp(z[v], z[v | (1 << jj)], U2, S2);
        }
        // wires 10..13: lane bit k <-> wire (13-k), shfl_xor butterflies.
        // lane-bit-k==0 holds 'a' (z' = c z - s p); ==1 holds 'b' (z' = c z + s p).
        #pragma unroll
        for (int k = 0; k < 4; ++k) {
            const int w = 13 - k;
            float c = CCa[l][w], s = SSa[l][w];
            float sg = ((l4 >> k) & 1) ? s : -s;
            u64 C2 = pk2(c, c), S2 = pk2(sg, sg);
            #pragma unroll
            for (int v = 0; v < 32; ++v) {
                u64 p = __shfl_xor_sync(0xffffffffu, z[v], 1 << k);
                z[v] = ffma2(C2, z[v], fmul2(S2, p));
            }
        }
        if (l == NL - 1) {
            // readout fused: <Z_0> sign = bit 13 of u = tid bit 8 (thread-constant)
            float ssum = 0.0f;
            #pragma unroll
            for (int v = 0; v < 32; ++v) {
                float zx, zy; up2(z[v], zx, zy);
                ssum = fmaf(zx, zx, fmaf(zy, zy, ssum));
            }
            acc = ((tid >> 8) & 1) ? -ssum : ssum;
        } else {
            #pragma unroll
            for (int v = 0; v < 32; ++v) stq[sb ^ SWc(v << 4)] = z[v];
            __syncthreads();
        }
    }

    // ---- block reduction ----
    #pragma unroll
    for (int o = 16; o > 0; o >>= 1) acc += __shfl_xor_sync(0xffffffffu, acc, o);
    if ((tid & 31) == 0) red[tid >> 5] = acc;
    __syncthreads();
    if (tid < 32) {
        float v = (tid < TPB / 32) ? red[tid] : 0.0f;
        #pragma unroll
        for (int o = 16; o > 0; o >>= 1) v += __shfl_xor_sync(0xffffffffu, v, o);
        if (tid == 0) out[b] = v;
    }
}

} // namespace

extern "C" void kernel_launch(void* const* d_in, const int* in_sizes, int n_in,
                              void* d_out, int out_size)
{
    const float* x  = (const float*)d_in[0];   // [B, 14]
    const float* fs = (const float*)d_in[1];   // [14]
    const float* vp = (const float*)d_in[2];   // [6, 14]
    float* out = (float*)d_out;                // [B, 1] float32

    const int B = in_sizes[0] / NQ;
    const size_t smem = (size_t)DIM * sizeof(u64);   // 128 KB dynamic
    cudaFuncSetAttribute(vqc_kernel, cudaFuncAttributeMaxDynamicSharedMemorySize,
                         (int)smem);
    vqc_kernel<<<B, TPB, smem>>>(x, fs, vp, out);
}

// round 11
// speedup vs baseline: 1.7096x; 1.1032x over previous
#include <cuda_runtime.h>

namespace {

constexpr int NQ  = 14;
constexpr int DIM = 1 << NQ;          // 16384 amplitudes
constexpr int TPB = 512;
constexpr int NL  = 6;

using u64 = unsigned long long;

// GF(2)-linear involutive bank swizzle (conflict-free per half-warp for all
// access patterns used below) and the ladder permutation h(t) = t ^ (t>>1)
// (psi_after_ladder(t) = psi_before(h(t)); prefix-parity over wires).
__device__   __forceinline__ int SW (int t) { return t ^ ((t >> 4) & 15) ^ ((t >> 8) & 15); }
__host__ __device__ constexpr int SWc(int t) { return t ^ ((t >> 4) & 15) ^ ((t >> 8) & 15); }
__host__ __device__ constexpr int Hc (int t) { return t ^ (t >> 1); }

// ---- packed f32x2 helpers ----
__device__ __forceinline__ u64 pk2(float lo, float hi) {
    u64 r; asm("mov.b64 %0, {%1, %2};" : "=l"(r) : "f"(lo), "f"(hi)); return r;
}
__device__ __forceinline__ void up2(u64 v, float& lo, float& hi) {
    asm("mov.b64 {%0, %1}, %2;" : "=f"(lo), "=f"(hi) : "l"(v));
}
__device__ __forceinline__ u64 ffma2(u64 a, u64 b, u64 c) {
    u64 d; asm("fma.rn.f32x2 %0, %1, %2, %3;" : "=l"(d) : "l"(a), "l"(b), "l"(c)); return d;
}
__device__ __forceinline__ float2 cmulf(float2 a, float2 b) {
    return make_float2(fmaf(a.x, b.x, -a.y * b.y), fmaf(a.x, b.y, a.y * b.x));
}

// Lifting (3-shear) RY on a pair (a = bit-0 side; ladder materialized => no
// signs anywhere): a += u b ; b += s a ; a += u b.
__device__ __forceinline__ void liftp(u64& a, u64& b, u64 U, u64 S) {
    a = ffma2(U, b, a);
    b = ffma2(S, a, b);
    a = ffma2(U, b, a);
}

__global__ void __launch_bounds__(TPB, 1)
vqc_kernel(const float* __restrict__ x, const float* __restrict__ fs,
           const float* __restrict__ vp, float* __restrict__ out)
{
    extern __shared__ u64 stq[];               // DIM swizzled amplitudes (128 KB)
    __shared__ float2 V0[NQ], V1[NQ];          // per-wire encoding 2-vectors
    __shared__ float2 TA[128], TB[128];        // subset-product tables
    __shared__ float UUa[NL][NQ], SSa[NL][NQ];
    __shared__ float red[TPB / 32];

    const int tid = threadIdx.x;
    const int b   = blockIdx.x;

    // ---- stage 1: encoding vectors + lifting constants ----
    if (tid < NQ) {
        float xi = x[b * NQ + tid];
        float s, c, sf, cf;
        sincosf(0.5f * xi, &s, &c);
        sincosf(0.5f * fs[tid] * xi, &sf, &cf);
        const float r = 0.70710678118654752440f;
        float pa = (c - s) * r;                // RY(x) H |0>
        float pb = (c + s) * r;
        V0[tid] = make_float2(cf * pa, -sf * pb);   // RX(fs*x) applied on top
        V1[tid] = make_float2(cf * pb, -sf * pa);
    } else if (tid >= 32 && tid < 32 + NL * NQ) {
        int k = tid - 32, l = k / NQ, w = k % NQ;
        float s, c;
        sincosf(0.5f * vp[l * NQ + w], &s, &c);
        SSa[l][w] = s;
        UUa[l][w] = (s == 0.0f) ? 0.0f : (c - 1.0f) / s;   // = -tan(phi/2)
    }
    __syncthreads();

    // ---- stage 2: subset-product tables ----
    if (tid < 128) {
        float2 acc = make_float2(1.0f, 0.0f);
        #pragma unroll
        for (int i = 7; i < 14; ++i) {
            int bit = (tid >> (13 - i)) & 1;
            acc = cmulf(acc, bit ? V1[i] : V0[i]);
        }
        TB[tid] = acc;
    } else if (tid < 256) {
        int h = tid - 128;
        float2 acc = make_float2(1.0f, 0.0f);
        #pragma unroll
        for (int i = 0; i < 7; ++i) {
            int bit = (h >> (6 - i)) & 1;
            acc = cmulf(acc, bit ? V1[i] : V0[i]);
        }
        TA[h] = acc;
    }
    __syncthreads();

    float acc = 0.0f;
    u64 z[32];

    #pragma unroll 1
    for (int l = 0; l < NL; ++l) {
        // ================= pass A: wires 0..4 (bits 13..9) =================
        // amp index u = (v<<9) | tid.  Load applies the ladder: z(u)=st(h(u)).
        // h and SW are GF(2)-linear -> addr = SW(h(tid)) ^ SWc(h(v<<9)).
        if (l == 0) {
            const int hr = Hc(tid);
            #pragma unroll
            for (int v = 0; v < 32; ++v) {
                int idx = hr ^ Hc(v << 9);     // encoded product state, ladder-mapped
                float2 a = cmulf(TA[idx >> 7], TB[idx & 127]);
                z[v] = pk2(a.x, a.y);
            }
        } else {
            const int la = SW(Hc(tid));
            #pragma unroll
            for (int v = 0; v < 32; ++v) z[v] = stq[la ^ SWc(Hc(v << 9))];
        }
        // rotate wires 0..4: reg bit jj <-> wire (4-jj); plain lifting
        #pragma unroll
        for (int jj = 0; jj < 5; ++jj) {
            const int w = 4 - jj;
            u64 U2 = pk2(UUa[l][w], UUa[l][w]);
            u64 S2 = pk2(SSa[l][w], SSa[l][w]);
            #pragma unroll
            for (int v = 0; v < 32; ++v)
                if (!(v & (1 << jj)))
                    liftp(z[v], z[v | (1 << jj)], U2, S2);
        }
        // h-gather crosses tiles: drain all loads before in-place stores
        if (l != 0) __syncthreads();
        {
            const int sa = SW(tid);
            #pragma unroll
            for (int v = 0; v < 32; ++v) stq[sa ^ SWc(v << 9)] = z[v];
        }
        __syncthreads();

        // ================= pass B: wires 5..9 (bits 8..4) =================
        // amp index u = (w5<<9) | (v<<4) | l4 ; w5 = tid>>4, l4 = tid&15.
        {
            const int sb = SW(((tid >> 4) << 9) | (tid & 15));
            #pragma unroll
            for (int v = 0; v < 32; ++v) z[v] = stq[sb ^ SWc(v << 4)];
            #pragma unroll
            for (int jj = 0; jj < 5; ++jj) {
                const int w = 9 - jj;
                u64 U2 = pk2(UUa[l][w], UUa[l][w]);
                u64 S2 = pk2(SSa[l][w], SSa[l][w]);
                #pragma unroll
                for (int v = 0; v < 32; ++v)
                    if (!(v & (1 << jj)))
                        liftp(z[v], z[v | (1 << jj)], U2, S2);
            }
            // stores go to exactly the loaded addresses: no barrier needed
            #pragma unroll
            for (int v = 0; v < 32; ++v) stq[sb ^ SWc(v << 4)] = z[v];
        }
        __syncthreads();

        // ======== pass C: wires 10..13 (bits 3..0), 16-amp register tiles ========
        // tile g: amps 16g+v at slots (16g ^ kg) ^ v, kg = (g&15)^((g>>4)&15).
        {
            u64 U2[4], S2[4];
            #pragma unroll
            for (int j = 0; j < 4; ++j) {
                const int w = 10 + j;
                U2[j] = pk2(UUa[l][w], UUa[l][w]);
                S2[j] = pk2(SSa[l][w], SSa[l][w]);
            }
            #pragma unroll
            for (int it = 0; it < 2; ++it) {
                const int g  = tid + it * TPB;          // 1024 tiles
                const int sb = (g << 4) ^ ((g & 15) ^ ((g >> 4) & 15));
                u64* t = z + it * 16;
                #pragma unroll
                for (int v = 0; v < 16; ++v) t[v] = stq[sb ^ v];
                #pragma unroll
                for (int j = 0; j < 4; ++j) {
                    const int bit = 3 - j;              // wire 10+j <-> bit 3-j
                    #pragma unroll
                    for (int v = 0; v < 16; ++v)
                        if (!(v & (1 << bit)))
                            liftp(t[v], t[v | (1 << bit)], U2[j], S2[j]);
                }
                if (l == NL - 1) {
                    // readout fused: <Z_0> sign = amp bit 13 = g bit 9
                    float ssum = 0.0f;
                    #pragma unroll
                    for (int v = 0; v < 16; ++v) {
                        float zx, zy; up2(t[v], zx, zy);
                        ssum = fmaf(zx, zx, fmaf(zy, zy, ssum));
                    }
                    acc += ((g >> 9) & 1) ? -ssum : ssum;
                } else {
                    #pragma unroll
                    for (int v = 0; v < 16; ++v) stq[sb ^ v] = t[v];
                }
            }
        }
        if (l != NL - 1) __syncthreads();
    }

    // ---- block reduction ----
    #pragma unroll
    for (int o = 16; o > 0; o >>= 1) acc += __shfl_xor_sync(0xffffffffu, acc, o);
    if ((tid & 31) == 0) red[tid >> 5] = acc;
    __syncthreads();
    if (tid < 32) {
        float v = (tid < TPB / 32) ? red[tid] : 0.0f;
        #pragma unroll
        for (int o = 16; o > 0; o >>= 1) v += __shfl_xor_sync(0xffffffffu, v, o);
        if (tid == 0) out[b] = v;
    }
}

} // namespace

extern "C" void kernel_launch(void* const* d_in, const int* in_sizes, int n_in,
                              void* d_out, int out_size)
{
    const float* x  = (const float*)d_in[0];   // [B, 14]
    const float* fs = (const float*)d_in[1];   // [14]
    const float* vp = (const float*)d_in[2];   // [6, 14]
    float* out = (float*)d_out;                // [B, 1] float32

    const int B = in_sizes[0] / NQ;
    const size_t smem = (size_t)DIM * sizeof(u64);   // 128 KB dynamic
    cudaFuncSetAttribute(vqc_kernel, cudaFuncAttributeMaxDynamicSharedMemorySize,
                         (int)smem);
    vqc_kernel<<<B, TPB, smem>>>(x, fs, vp, out);
}

// round 12
// speedup vs baseline: 1.7545x; 1.0263x over previous
#include <cuda_runtime.h>

namespace {

constexpr int NQ  = 14;
constexpr int DIM = 1 << NQ;          // 16384 amplitudes
constexpr int TPB = 512;
constexpr int NL  = 6;

using u64 = unsigned long long;

// GF(2)-linear involutive bank swizzle (conflict-free per half-warp for all
// access patterns below).
__device__   __forceinline__ int SW (int t) { return t ^ ((t >> 4) & 15) ^ ((t >> 8) & 15); }
__host__ __device__ constexpr int SWc(int t) { return t ^ ((t >> 4) & 15) ^ ((t >> 8) & 15); }
// In-tile ladder gather maps (compile-time register relabels):
// C(a,a+1) chains inside a 5-/4-bit tile compose to v ^ (v>>1).
__host__ __device__ constexpr int Q5(int v) { return (v ^ (v >> 1)) & 31; }
__host__ __device__ constexpr int Q4(int v) { return (v ^ (v >> 1)) & 15; }

// ---- packed f32x2 helpers ----
__device__ __forceinline__ u64 pk2(float lo, float hi) {
    u64 r; asm("mov.b64 %0, {%1, %2};" : "=l"(r) : "f"(lo), "f"(hi)); return r;
}
__device__ __forceinline__ void up2(u64 v, float& lo, float& hi) {
    asm("mov.b64 {%0, %1}, %2;" : "=f"(lo), "=f"(hi) : "l"(v));
}
__device__ __forceinline__ u64 ffma2(u64 a, u64 b, u64 c) {
    u64 d; asm("fma.rn.f32x2 %0, %1, %2, %3;" : "=l"(d) : "l"(a), "l"(b), "l"(c)); return d;
}
__device__ __forceinline__ float2 cmulf(float2 a, float2 b) {
    return make_float2(fmaf(a.x, b.x, -a.y * b.y), fmaf(a.x, b.y, a.y * b.x));
}

// Lifting (3-shear) RY on a pair (a = 0-side): a += u b ; b += s a ; a += u b.
__device__ __forceinline__ void liftp(u64& a, u64& b, u64 U, u64 S) {
    a = ffma2(U, b, a);
    b = ffma2(S, a, b);
    a = ffma2(U, b, a);
}

__global__ void __launch_bounds__(TPB, 1)
vqc_kernel(const float* __restrict__ x, const float* __restrict__ fs,
           const float* __restrict__ vp, float* __restrict__ out)
{
    extern __shared__ u64 stq[];               // DIM swizzled amplitudes (128 KB)
    __shared__ float2 V0[NQ], V1[NQ];          // per-wire encoding 2-vectors
    __shared__ float2 TA[128], TB[128];        // subset-product tables
    __shared__ float UUa[NL][NQ], SSa[NL][NQ]; // lifting consts u=(c-1)/s, s
    __shared__ float red[TPB / 32];

    const int tid = threadIdx.x;
    const int b   = blockIdx.x;

    // ---- stage 1: encoding vectors + lifting constants ----
    if (tid < NQ) {
        float xi = x[b * NQ + tid];
        float s, c, sf, cf;
        sincosf(0.5f * xi, &s, &c);
        sincosf(0.5f * fs[tid] * xi, &sf, &cf);
        const float r = 0.70710678118654752440f;
        float pa = (c - s) * r;                // RY(x) H |0>
        float pb = (c + s) * r;
        V0[tid] = make_float2(cf * pa, -sf * pb);   // RX(fs*x) applied on top
        V1[tid] = make_float2(cf * pb, -sf * pa);
    } else if (tid >= 32 && tid < 32 + NL * NQ) {
        int k = tid - 32, l = k / NQ, w = k % NQ;
        float s, c;
        sincosf(0.5f * vp[l * NQ + w], &s, &c);
        SSa[l][w] = s;
        UUa[l][w] = (s == 0.0f) ? 0.0f : (c - 1.0f) / s;   // = -tan(phi/2)
    }
    __syncthreads();

    // ---- stage 2: subset-product tables ----
    if (tid < 128) {
        float2 acc = make_float2(1.0f, 0.0f);
        #pragma unroll
        for (int i = 7; i < 14; ++i) {
            int bit = (tid >> (13 - i)) & 1;
            acc = cmulf(acc, bit ? V1[i] : V0[i]);
        }
        TB[tid] = acc;
    } else if (tid < 256) {
        int h = tid - 128;
        float2 acc = make_float2(1.0f, 0.0f);
        #pragma unroll
        for (int i = 0; i < 7; ++i) {
            int bit = (h >> (6 - i)) & 1;
            acc = cmulf(acc, bit ? V1[i] : V0[i]);
        }
        TA[h] = acc;
    }
    __syncthreads();

    float acc = 0.0f;
    u64 z[32];

    #pragma unroll 1
    for (int l = 0; l < NL; ++l) {
        // ========== pass A: wires 0..3 (+deferred RY4^{l-1}), bits 13..9 ==========
        // amp = (v<<9)|tid ; loads and stores hit the SAME addresses.
        {
            const int baseA = SW(tid);
            if (l == 0) {
                float2 tb = TB[tid & 127];
                #pragma unroll
                for (int v = 0; v < 32; ++v) {
                    float2 a = cmulf(TA[(v << 2) | (tid >> 7)], tb);
                    z[v] = pk2(a.x, a.y);
                }
            } else {
                #pragma unroll
                for (int v = 0; v < 32; ++v) z[v] = stq[baseA ^ SWc(v << 9)];
                // deferred RY4^{l-1}: pairs on amp bit9 = v bit0
                u64 U2 = pk2(UUa[l-1][4], UUa[l-1][4]);
                u64 S2 = pk2(SSa[l-1][4], SSa[l-1][4]);
                #pragma unroll
                for (int v = 0; v < 32; v += 2) liftp(z[v], z[v | 1], U2, S2);
            }
            // ladder C01..C34 = register relabel Q5; then RY0..3 on p bits 4..1
            #pragma unroll
            for (int k = 4; k >= 1; --k) {
                const int w = 4 - k;
                u64 U2 = pk2(UUa[l][w], UUa[l][w]);
                u64 S2 = pk2(SSa[l][w], SSa[l][w]);
                #pragma unroll
                for (int p = 0; p < 32; ++p)
                    if (!(p & (1 << k)))
                        liftp(z[Q5(p)], z[Q5(p | (1 << k))], U2, S2);
            }
            #pragma unroll
            for (int p = 0; p < 32; ++p) stq[baseA ^ SWc(p << 9)] = z[Q5(p)];
        }
        __syncthreads();

        // ========== pass B: wires 5..8 (+RY9^{l-1}, C45 fold), bits 8..4 ==========
        // amp = (f5<<9)|(v<<4)|f4, f5 = tid>>4, f4 = tid&15.
        {
            const int fix  = ((tid >> 4) << 9) | (tid & 15);
            const int bst  = SW(fix);
            const int bld  = bst ^ (((tid >> 4) & 1) ? SWc(1 << 8) : 0);  // C45 fold
            #pragma unroll
            for (int v = 0; v < 32; ++v) z[v] = stq[bld ^ SWc(v << 4)];
            if (l) {
                // deferred RY9^{l-1}: pairs on amp bit4 = v bit0 (fold-invariant)
                u64 U2 = pk2(UUa[l-1][9], UUa[l-1][9]);
                u64 S2 = pk2(SSa[l-1][9], SSa[l-1][9]);
                #pragma unroll
                for (int v = 0; v < 32; v += 2) liftp(z[v], z[v | 1], U2, S2);
            }
            // ladder C56..C89 = relabel Q5; RY5..8 on p bits 4..1
            #pragma unroll
            for (int k = 4; k >= 1; --k) {
                const int w = 9 - k;
                u64 U2 = pk2(UUa[l][w], UUa[l][w]);
                u64 S2 = pk2(SSa[l][w], SSa[l][w]);
                #pragma unroll
                for (int p = 0; p < 32; ++p)
                    if (!(p & (1 << k)))
                        liftp(z[Q5(p)], z[Q5(p | (1 << k))], U2, S2);
            }
            #pragma unroll
            for (int p = 0; p < 32; ++p) stq[bst ^ SWc(p << 4)] = z[Q5(p)];
        }
        __syncthreads();

        // ========== pass C: wires 10..13 (C910 fold), bits 3..0 ==========
        // Tile assignment: g bit4 = tid>>8 so group h owns amps bit8 = h
        // (matches pass A's reads -> split barrier below is safe).
        #pragma unroll
        for (int it = 0; it < 2; ++it) {
            const int g   = (it << 9) | ((tid & 0xF0) << 1)
                          | (((tid >> 8) & 1) << 4) | (tid & 15);
            const int kg  = (g & 15) ^ ((g >> 4) & 15);
            const int sbn = (g << 4) ^ kg;                 // natural swizzled base
            const int sbl = sbn ^ ((g & 1) ? 8 : 0);       // C910 fold (ctrl = amp bit4)
            u64* t = z + it * 16;
            #pragma unroll
            for (int w = 0; w < 16; ++w) t[w] = stq[sbl ^ w];
            // ladder C10-11..C12-13 = relabel Q4; RY10..13 on p bits 3..0
            #pragma unroll
            for (int k = 3; k >= 0; --k) {
                const int w = 13 - k;
                u64 U2 = pk2(UUa[l][w], UUa[l][w]);
                u64 S2 = pk2(SSa[l][w], SSa[l][w]);
                #pragma unroll
                for (int p = 0; p < 16; ++p)
                    if (!(p & (1 << k)))
                        liftp(t[Q4(p)], t[Q4(p | (1 << k))], U2, S2);
            }
            if (l == NL - 1) {
                // readout: <Z_0> sign = amp bit13 = g bit9 = it.
                // (final RY4^5 / RY9^5 skipped: they mix equal-sign pairs only)
                float ssum = 0.0f;
                #pragma unroll
                for (int p = 0; p < 16; ++p) {
                    float zx, zy; up2(t[p], zx, zy);
                    ssum = fmaf(zx, zx, fmaf(zy, zy, ssum));
                }
                acc += it ? -ssum : ssum;
            } else {
                #pragma unroll
                for (int p = 0; p < 16; ++p) stq[sbn ^ p] = t[Q4(p)];
            }
        }
        if (l != NL - 1) {
            // split seam C->A: group h (tid>>8) only needs its own half done
            if (tid < 256) { asm volatile("bar.sync 1, 256;" ::: "memory"); }
            else           { asm volatile("bar.sync 2, 256;" ::: "memory"); }
        }
    }

    // ---- block reduction ----
    #pragma unroll
    for (int o = 16; o > 0; o >>= 1) acc += __shfl_xor_sync(0xffffffffu, acc, o);
    if ((tid & 31) == 0) red[tid >> 5] = acc;
    __syncthreads();
    if (tid < 32) {
        float v = (tid < TPB / 32) ? red[tid] : 0.0f;
        #pragma unroll
        for (int o = 16; o > 0; o >>= 1) v += __shfl_xor_sync(0xffffffffu, v, o);
        if (tid == 0) out[b] = v;
    }
}

} // namespace

extern "C" void kernel_launch(void* const* d_in, const int* in_sizes, int n_in,
                              void* d_out, int out_size)
{
    const float* x  = (const float*)d_in[0];   // [B, 14]
    const float* fs = (const float*)d_in[1];   // [14]
    const float* vp = (const float*)d_in[2];   // [6, 14]
    float* out = (float*)d_out;                // [B, 1] float32

    const int B = in_sizes[0] / NQ;
    const size_t smem = (size_t)DIM * sizeof(u64);   // 128 KB dynamic
    cudaFuncSetAttribute(vqc_kernel, cudaFuncAttributeMaxDynamicSharedMemorySize,
                         (int)smem);
    vqc_kernel<<<B, TPB, smem>>>(x, fs, vp, out);
}